// round 6
// baseline (speedup 1.0000x reference)
#include <cuda_runtime.h>
#include <cstdint>
#include <math.h>

// Problem constants
#define NB   16
#define NC   512
#define NL   4096
#define ND   384
#define NTOK 256
#define NROWS 4096      // NB*NTOK
#define NINNER 512
#define NFF  1536
#define NHEADS 8
#define NDH  64

// Scratch (device globals; allocation-free)
__device__ float g_h [NROWS*ND];        // residual stream (fp32)
__device__ float g_y [NROWS*NFF];       // qkv / ff intermediate / conv gather
__device__ float g_t1[NROWS*NINNER];    // xpT / attn out / hp
__device__ float g_t2[NROWS*ND];        // ln out
__device__ float g_t3[NROWS*ND];        // conv out
__device__ float g_wqkvR[2*ND*NFF];     // rounded [K=384][N=1536] per layer
__device__ float g_ffw1R[2*ND*NFF];     // rounded [K=384][N=1536]
__device__ float g_ffw2R[2*NFF*ND];     // rounded [K=1536][N=384]
__device__ float g_woutR[2*NINNER*ND];  // rounded [K=512][N=384]
__device__ float g_wA[NC*ND];           // proj_in_w^T rounded [K=512][N=384]
__device__ float g_wB[ND*NC];           // proj_out_w^T rounded [K=384][N=512]
__device__ float g_wt[3*ND*ND];         // conv weight rounded [K=1152][N=384]

__device__ __forceinline__ float gelu_exact(float v) { return v * normcdff(v); }

__device__ __forceinline__ unsigned f2tf(float f) {
    unsigned u; asm("cvt.rna.tf32.f32 %0, %1;" : "=r"(u) : "f"(f)); return u;
}
__device__ __forceinline__ float rndf(float f) { return __uint_as_float(f2tf(f)); }

__device__ __forceinline__ void mma_tf32(float (&d)[4], const unsigned (&a)[4],
                                         const unsigned (&b)[2]) {
    asm volatile(
        "mma.sync.aligned.m16n8k8.row.col.f32.tf32.tf32.f32 "
        "{%0,%1,%2,%3}, {%4,%5,%6,%7}, {%8,%9}, {%0,%1,%2,%3};\n"
        : "+f"(d[0]), "+f"(d[1]), "+f"(d[2]), "+f"(d[3])
        : "r"(a[0]), "r"(a[1]), "r"(a[2]), "r"(a[3]), "r"(b[0]), "r"(b[1]));
}

#define CP_ASYNC16(dst, src) \
    asm volatile("cp.async.ca.shared.global [%0], [%1], 16;\n" :: "r"(dst), "l"(src))
#define CP_COMMIT() asm volatile("cp.async.commit_group;\n" ::)
#define CP_WAIT2()  asm volatile("cp.async.wait_group 2;\n" ::)

// ---------------------------------------------------------------------------
// tf32 mma.sync GEMM, 4-stage cp.async pipeline.
//   C[M,N-tile] = f(A[M,K] @ Bw[K,N] + bias) (+Cin if ACC), RND rounds output.
// WR=4: BM=128 (warps 4x2, warp tile 32x64); WR=2: BM=64 (warps 2x4, 32x32).
// BN=128 fixed. 256 threads. Inputs assumed pre-rounded to tf32.
// ---------------------------------------------------------------------------
template<int WR, int ACT, bool ACC, bool RND>
__global__ __launch_bounds__(256, 2) void tg(
    const float* __restrict__ A, const float* __restrict__ Bw,
    const float* __restrict__ bias, const float* __restrict__ Cin,
    float* __restrict__ C, int M, int N, int K)
{
    constexpr int BM  = WR * 32;
    constexpr int WC  = 8 / WR;           // warp cols
    constexpr int NTn = 16 / WC;          // n-tiles per warp (8 or 4)
    constexpr int SA  = 20;               // A smem stride (floats)
    constexpr int SB  = 136;              // B smem stride (floats)
    constexpr int ASZ = BM * SA;
    constexpr int STG = BM * SA + 16 * SB; // floats per stage
    constexpr int ALD = BM / 64;          // A float4 loads per thread

    extern __shared__ float sm[];

    const int tid = threadIdx.x;
    const int warp = tid >> 5, lane = tid & 31;
    const int wr = warp / WC, wc = warp % WC;
    const int m0 = blockIdx.y * BM, n0 = blockIdx.x * 128;
    const int T = K >> 4;

    float acc[2][NTn][4];
#pragma unroll
    for (int mt = 0; mt < 2; mt++)
#pragma unroll
        for (int nt = 0; nt < NTn; nt++)
#pragma unroll
            for (int i = 0; i < 4; i++) acc[mt][nt][i] = 0.f;

    const int a_r = tid >> 2, a_c = (tid & 3) << 2;
    const int b_r = tid >> 5, b_c = (tid & 31) << 2;

    auto issue = [&](int t) {
        if (t >= T) return;
        float* st = sm + (size_t)(t & 3) * STG;
        const float* Ag = A + (size_t)m0 * K + t * 16;
#pragma unroll
        for (int j = 0; j < ALD; j++) {
            int row = a_r + j * 64;
            uint32_t d = (uint32_t)__cvta_generic_to_shared(st + row * SA + a_c);
            CP_ASYNC16(d, Ag + (size_t)row * K + a_c);
        }
        const float* Bg = Bw + (size_t)(t * 16) * N + n0;
#pragma unroll
        for (int j = 0; j < 2; j++) {
            int row = b_r + j * 8;
            uint32_t d = (uint32_t)__cvta_generic_to_shared(st + ASZ + row * SB + b_c);
            CP_ASYNC16(d, Bg + (size_t)row * N + b_c);
        }
        CP_COMMIT();
    };

    issue(0); issue(1); issue(2);

    for (int t = 0; t < T; t++) {
        CP_WAIT2();
        __syncthreads();
        issue(t + 3);

        const float* As = sm + (size_t)(t & 3) * STG;
        const float* Bs = As + ASZ;
#pragma unroll
        for (int kk = 0; kk < 2; kk++) {
            const int k = kk * 8 + (lane & 3);
            const int r = wr * 32 + (lane >> 2);
            unsigned af[2][4], bf[NTn][2];
#pragma unroll
            for (int mt = 0; mt < 2; mt++) {
                af[mt][0] = __float_as_uint(As[(r + mt * 16) * SA + k]);
                af[mt][1] = __float_as_uint(As[(r + mt * 16 + 8) * SA + k]);
                af[mt][2] = __float_as_uint(As[(r + mt * 16) * SA + k + 4]);
                af[mt][3] = __float_as_uint(As[(r + mt * 16 + 8) * SA + k + 4]);
            }
#pragma unroll
            for (int nt = 0; nt < NTn; nt++) {
                const int c = wc * (NTn * 8) + nt * 8 + (lane >> 2);
                bf[nt][0] = __float_as_uint(Bs[k * SB + c]);
                bf[nt][1] = __float_as_uint(Bs[(k + 4) * SB + c]);
            }
#pragma unroll
            for (int mt = 0; mt < 2; mt++)
#pragma unroll
                for (int nt = 0; nt < NTn; nt++)
                    mma_tf32(acc[mt][nt], af[mt], bf[nt]);
        }
    }

    // epilogue
#pragma unroll
    for (int mt = 0; mt < 2; mt++) {
#pragma unroll
        for (int nt = 0; nt < NTn; nt++) {
#pragma unroll
            for (int half = 0; half < 2; half++) {
                const int row = m0 + wr * 32 + mt * 16 + (lane >> 2) + half * 8;
                const int col = n0 + wc * (NTn * 8) + nt * 8 + (lane & 3) * 2;
                float2 r;
                r.x = acc[mt][nt][half * 2];
                r.y = acc[mt][nt][half * 2 + 1];
                if (bias) { r.x += bias[col]; r.y += bias[col + 1]; }
                if (ACT == 1) { r.x = gelu_exact(r.x); r.y = gelu_exact(r.y); }
                if (ACC) {
                    const float* cp = Cin + (size_t)row * N + col;
                    r.x += cp[0]; r.y += cp[1];
                }
                if (RND) { r.x = rndf(r.x); r.y = rndf(r.y); }
                *(float2*)(C + (size_t)row * N + col) = r;
            }
        }
    }
}

// ---------------------------------------------------------------------------
// Round-copy: out[i] = tf32(in[i]) (vectorized)
// ---------------------------------------------------------------------------
__global__ __launch_bounds__(256) void rcopy_kernel(const float* __restrict__ in,
                                                    float* __restrict__ out, int n4)
{
    int i = blockIdx.x * 256 + threadIdx.x;
    if (i >= n4) return;
    float4 v = ((const float4*)in)[i];
    v.x = rndf(v.x); v.y = rndf(v.y); v.z = rndf(v.z); v.w = rndf(v.w);
    ((float4*)out)[i] = v;
}

// ---------------------------------------------------------------------------
// Tiled transpose + round: src[R][Cc] -> dst[Cc][R]
// ---------------------------------------------------------------------------
__global__ __launch_bounds__(256) void transpose_kernel(const float* __restrict__ src,
                                                        float* __restrict__ dst,
                                                        int R, int Cc)
{
    __shared__ float t[32][33];
    int c = blockIdx.x * 32 + threadIdx.x;
    int r = blockIdx.y * 32 + threadIdx.y;
#pragma unroll
    for (int i = 0; i < 32; i += 8)
        t[threadIdx.y + i][threadIdx.x] = src[(size_t)(r + i) * Cc + c];
    __syncthreads();
    int co = blockIdx.y * 32 + threadIdx.x;
    int ro = blockIdx.x * 32 + threadIdx.y;
#pragma unroll
    for (int i = 0; i < 32; i += 8)
        dst[(size_t)(ro + i) * R + co] = rndf(t[threadIdx.x][threadIdx.y + i]);
}

// Conv weight: lw[dout,din,k] -> wt[(k*384+din)][dout]  ([K=1152][N=384]), rounded
__global__ __launch_bounds__(256) void wtrans_kernel(const float* __restrict__ lw,
                                                     float* __restrict__ wt)
{
    int idx = blockIdx.x * 256 + threadIdx.x;
    if (idx >= 3 * ND * ND) return;
    int krow = idx / ND;                 // k*384+din
    int dout = idx - krow * ND;
    int k = krow / ND, din = krow - k * ND;
    wt[idx] = rndf(lw[(dout * ND + din) * 3 + k]);
}

// ---------------------------------------------------------------------------
// Pool: x[B,C,L] -> xpT[(b*256+n), c], mean over windows of 16, tf32-rounded
// ---------------------------------------------------------------------------
__global__ __launch_bounds__(256) void pool_kernel(const float* __restrict__ x,
                                                   float* __restrict__ xpT)
{
    int bc = blockIdx.x;
    int b = bc >> 9, c = bc & 511;
    const float4* src = (const float4*)(x + (size_t)bc * NL) + threadIdx.x * 4;
    float s = 0.f;
#pragma unroll
    for (int j = 0; j < 4; j++) {
        float4 v = src[j];
        s += v.x + v.y + v.z + v.w;
    }
    xpT[((size_t)(b * NTOK + threadIdx.x)) * NC + c] = rndf(s * (1.f / 16.f));
}

// ---------------------------------------------------------------------------
// LayerNorm over last dim (384). Warp per row. RND: tf32-round outputs.
// ---------------------------------------------------------------------------
template<bool RND>
__global__ __launch_bounds__(256) void ln_kernel(const float* __restrict__ in,
                                                 const float* __restrict__ g,
                                                 const float* __restrict__ b,
                                                 float* __restrict__ out)
{
    const int wid = threadIdx.x >> 5, lane = threadIdx.x & 31;
    const int row = blockIdx.x * 8 + wid;
    const float* xr = in + (size_t)row * ND;
    float4 v0 = *(const float4*)(xr + lane * 4);
    float4 v1 = *(const float4*)(xr + 128 + lane * 4);
    float4 v2 = *(const float4*)(xr + 256 + lane * 4);
    float s = v0.x + v0.y + v0.z + v0.w + v1.x + v1.y + v1.z + v1.w
            + v2.x + v2.y + v2.z + v2.w;
    float q = v0.x*v0.x + v0.y*v0.y + v0.z*v0.z + v0.w*v0.w
            + v1.x*v1.x + v1.y*v1.y + v1.z*v1.z + v1.w*v1.w
            + v2.x*v2.x + v2.y*v2.y + v2.z*v2.z + v2.w*v2.w;
#pragma unroll
    for (int o = 16; o; o >>= 1) {
        s += __shfl_xor_sync(0xFFFFFFFFu, s, o);
        q += __shfl_xor_sync(0xFFFFFFFFu, q, o);
    }
    const float mean = s * (1.f / ND);
    const float var  = q * (1.f / ND) - mean * mean;
    const float inv  = rsqrtf(var + 1e-5f);
    float* orow = out + (size_t)row * ND;
#pragma unroll
    for (int j = 0; j < 3; j++) {
        int col = j * 128 + lane * 4;
        float4 v = (j == 0) ? v0 : (j == 1) ? v1 : v2;
        float4 gg = *(const float4*)(g + col);
        float4 bb = *(const float4*)(b + col);
        float4 r;
        r.x = (v.x - mean) * inv * gg.x + bb.x;
        r.y = (v.y - mean) * inv * gg.y + bb.y;
        r.z = (v.z - mean) * inv * gg.z + bb.z;
        r.w = (v.w - mean) * inv * gg.w + bb.w;
        if (RND) { r.x = rndf(r.x); r.y = rndf(r.y); r.z = rndf(r.z); r.w = rndf(r.w); }
        *(float4*)(orow + col) = r;
    }
}

// ---------------------------------------------------------------------------
// Linear attention per (b,h); output tf32-rounded (feeds wout GEMM)
// ---------------------------------------------------------------------------
__device__ __forceinline__ void r1u(float (&acc)[4][4], float a0, float a1,
                                    float a2, float a3, const float4 b)
{
    acc[0][0] += a0 * b.x; acc[0][1] += a0 * b.y; acc[0][2] += a0 * b.z; acc[0][3] += a0 * b.w;
    acc[1][0] += a1 * b.x; acc[1][1] += a1 * b.y; acc[1][2] += a1 * b.z; acc[1][3] += a1 * b.w;
    acc[2][0] += a2 * b.x; acc[2][1] += a2 * b.y; acc[2][2] += a2 * b.z; acc[2][3] += a2 * b.w;
    acc[3][0] += a3 * b.x; acc[3][1] += a3 * b.y; acc[3][2] += a3 * b.z; acc[3][3] += a3 * b.w;
}

__global__ __launch_bounds__(256) void attn_kernel(const float* __restrict__ qkv,
                                                   const float* __restrict__ rf,
                                                   float* __restrict__ o)
{
    __shared__ float rf_s[4096];
    __shared__ float bufA[4096];
    __shared__ float bufB[4096];
    const int tid = threadIdx.x;
    const int bh = blockIdx.x;
    const int b = bh >> 3, h = bh & 7;
    const int tq = tid >> 4, tr = tid & 15;

#pragma unroll
    for (int j = 0; j < 4; j++)
        ((float4*)rf_s)[tid + j * 256] = ((const float4*)rf)[tid + j * 256];

    const float* base = qkv + (size_t)b * NTOK * NFF + h * NDH;

    float kv[4][4];
#pragma unroll
    for (int i = 0; i < 4; i++)
#pragma unroll
        for (int j = 0; j < 4; j++) kv[i][j] = 0.f;

    for (int n0 = 0; n0 < NTOK; n0 += 64) {
        __syncthreads();
#pragma unroll
        for (int j = 0; j < 4; j++) {
            int lin = tid + j * 256;
            int rowi = lin >> 4, c4 = (lin & 15) << 2;
            const float* rp = base + (size_t)(n0 + rowi) * NFF;
            float4 kk = *(const float4*)(rp + NINNER + c4);
            kk.x = fmaxf(kk.x, 0.f); kk.y = fmaxf(kk.y, 0.f);
            kk.z = fmaxf(kk.z, 0.f); kk.w = fmaxf(kk.w, 0.f);
            *(float4*)&bufA[rowi * 64 + c4] = kk;
            *(float4*)&bufB[rowi * 64 + c4] = *(const float4*)(rp + 2 * NINNER + c4);
        }
        __syncthreads();
#pragma unroll 8
        for (int nn = 0; nn < 64; nn++) {
            float4 ka = *(const float4*)&bufA[nn * 64 + tq * 4];
            float4 vb = *(const float4*)&bufB[nn * 64 + tr * 4];
            r1u(kv, ka.x, ka.y, ka.z, ka.w, vb);
        }
    }
    __syncthreads();
#pragma unroll
    for (int i = 0; i < 4; i++) {
        float4 v = make_float4(kv[i][0], kv[i][1], kv[i][2], kv[i][3]);
        *(float4*)&bufA[(tq * 4 + i) * 64 + tr * 4] = v;
    }
    __syncthreads();

    float w1[4][4];
#pragma unroll
    for (int i = 0; i < 4; i++)
#pragma unroll
        for (int j = 0; j < 4; j++) w1[i][j] = 0.f;
#pragma unroll 8
    for (int dk = 0; dk < 64; dk++) {
        float4 rm = *(const float4*)&rf_s[dk * 64 + tq * 4];
        float4 kd = *(const float4*)&bufA[dk * 64 + tr * 4];
        r1u(w1, rm.x, rm.y, rm.z, rm.w, kd);
    }
    __syncthreads();
#pragma unroll
    for (int i = 0; i < 4; i++) {
        float4 v = make_float4(w1[i][0], w1[i][1], w1[i][2], w1[i][3]);
        *(float4*)&bufB[(tq * 4 + i) * 64 + tr * 4] = v;
    }
    __syncthreads();

    float w2[4][4];
#pragma unroll
    for (int i = 0; i < 4; i++)
#pragma unroll
        for (int j = 0; j < 4; j++) w2[i][j] = 0.f;
#pragma unroll 8
    for (int m = 0; m < 64; m++) {
        float4 wd = *(const float4*)&bufB[m * 64 + tr * 4];
        float r0 = rf_s[(tq * 4 + 0) * 64 + m];
        float r1 = rf_s[(tq * 4 + 1) * 64 + m];
        float r2 = rf_s[(tq * 4 + 2) * 64 + m];
        float r3 = rf_s[(tq * 4 + 3) * 64 + m];
        r1u(w2, r0, r1, r2, r3, wd);
    }
    __syncthreads();
#pragma unroll
    for (int i = 0; i < 4; i++) {
        float4 v = make_float4(w2[i][0], w2[i][1], w2[i][2], w2[i][3]);
        *(float4*)&bufA[(tq * 4 + i) * 64 + tr * 4] = v;
    }
    __syncthreads();

    for (int n0 = 0; n0 < NTOK; n0 += 64) {
#pragma unroll
        for (int j = 0; j < 4; j++) {
            int lin = tid + j * 256;
            int rowi = lin >> 4, c4 = (lin & 15) << 2;
            const float* rp = base + (size_t)(n0 + rowi) * NFF;
            float4 qq = *(const float4*)(rp + c4);
            qq.x = fmaxf(qq.x, 0.f) * 0.125f; qq.y = fmaxf(qq.y, 0.f) * 0.125f;
            qq.z = fmaxf(qq.z, 0.f) * 0.125f; qq.w = fmaxf(qq.w, 0.f) * 0.125f;
            *(float4*)&bufB[rowi * 64 + c4] = qq;
        }
        __syncthreads();
        float oc[4][4];
#pragma unroll
        for (int i = 0; i < 4; i++)
#pragma unroll
            for (int j = 0; j < 4; j++) oc[i][j] = 0.f;
#pragma unroll 8
        for (int dq = 0; dq < 64; dq++) {
            float4 wd = *(const float4*)&bufA[dq * 64 + tr * 4];
            float q0 = bufB[(tq * 4 + 0) * 64 + dq];
            float q1 = bufB[(tq * 4 + 1) * 64 + dq];
            float q2 = bufB[(tq * 4 + 2) * 64 + dq];
            float q3 = bufB[(tq * 4 + 3) * 64 + dq];
            r1u(oc, q0, q1, q2, q3, wd);
        }
#pragma unroll
        for (int i = 0; i < 4; i++) {
            float4 v = make_float4(rndf(oc[i][0]), rndf(oc[i][1]),
                                   rndf(oc[i][2]), rndf(oc[i][3]));
            *(float4*)(o + (size_t)(b * NTOK + n0 + tq * 4 + i) * NINNER + h * NDH + tr * 4) = v;
        }
        __syncthreads();
    }
}

// ---------------------------------------------------------------------------
// Conv gather (rounded): A_ext[r] = [h[r-1] | h[r] | h[r+1]] with batch-edge zeros
// ---------------------------------------------------------------------------
__global__ __launch_bounds__(256) void gather_kernel(const float* __restrict__ h,
                                                     float* __restrict__ aext)
{
    int idx = blockIdx.x * 256 + threadIdx.x;   // float4 index
    int r = idx / 288;
    int c4 = idx - r * 288;
    int seg = c4 / 96;
    int col = (c4 - seg * 96) * 4;
    int n = r & 255;
    int src = r + seg - 1;
    float4 v = make_float4(0.f, 0.f, 0.f, 0.f);
    bool ok = (seg == 1) || (seg == 0 && n > 0) || (seg == 2 && n < 255);
    if (ok) {
        v = *(const float4*)(h + (size_t)src * ND + col);
        v.x = rndf(v.x); v.y = rndf(v.y); v.z = rndf(v.z); v.w = rndf(v.w);
    }
    *(float4*)(aext + (size_t)r * 1152 + c4 * 4) = v;
}

// ---------------------------------------------------------------------------
// Final: out[b,c,l] = interp(hp)[b,c,l] + x[b,c,l]
// ---------------------------------------------------------------------------
__global__ __launch_bounds__(256) void final_kernel(const float* __restrict__ hp,
                                                    const float* __restrict__ x,
                                                    float* __restrict__ out)
{
    size_t idx = (size_t)blockIdx.x * 256 + threadIdx.x;
    int l = (int)(idx & 4095);
    int c = (int)((idx >> 12) & 511);
    int b = (int)(idx >> 21);
    float src = fmaxf((l + 0.5f) * 0.0625f - 0.5f, 0.f);
    int i0 = (int)src;
    float w = src - (float)i0;
    int i1 = min(i0 + 1, 255);
    float v0 = hp[(size_t)(b * NTOK + i0) * NC + c];
    float v1 = hp[(size_t)(b * NTOK + i1) * NC + c];
    out[idx] = v0 * (1.f - w) + v1 * w + x[idx];
}

// ---------------------------------------------------------------------------
// Host orchestration
// ---------------------------------------------------------------------------
extern "C" void kernel_launch(void* const* d_in, const int* in_sizes, int n_in,
                              void* d_out, int out_size)
{
    const float* x          = (const float*)d_in[0];
    const float* proj_in_w  = (const float*)d_in[1];
    const float* proj_in_b  = (const float*)d_in[2];
    const float* norm_in_g  = (const float*)d_in[3];
    const float* norm_in_b  = (const float*)d_in[4];
    const float* ln1_g      = (const float*)d_in[5];
    const float* ln1_b      = (const float*)d_in[6];
    const float* wqkv       = (const float*)d_in[7];
    const float* rf         = (const float*)d_in[8];
    const float* wout       = (const float*)d_in[9];
    const float* bout       = (const float*)d_in[10];
    const float* ln2_g      = (const float*)d_in[11];
    const float* ln2_b      = (const float*)d_in[12];
    const float* ffw1       = (const float*)d_in[13];
    const float* ffb1       = (const float*)d_in[14];
    const float* ffw2       = (const float*)d_in[15];
    const float* ffb2       = (const float*)d_in[16];
    const float* local_w    = (const float*)d_in[17];
    const float* local_b    = (const float*)d_in[18];
    const float* norm_out_g = (const float*)d_in[19];
    const float* norm_out_b = (const float*)d_in[20];
    const float* proj_out_w = (const float*)d_in[21];
    const float* proj_out_b = (const float*)d_in[22];
    float* out = (float*)d_out;

    float *h_, *y_, *t1_, *t2_, *t3_;
    float *wqkvR_, *ffw1R_, *ffw2R_, *woutR_, *wA_, *wB_, *wt_;
    cudaGetSymbolAddress((void**)&h_,     g_h);
    cudaGetSymbolAddress((void**)&y_,     g_y);
    cudaGetSymbolAddress((void**)&t1_,    g_t1);
    cudaGetSymbolAddress((void**)&t2_,    g_t2);
    cudaGetSymbolAddress((void**)&t3_,    g_t3);
    cudaGetSymbolAddress((void**)&wqkvR_, g_wqkvR);
    cudaGetSymbolAddress((void**)&ffw1R_, g_ffw1R);
    cudaGetSymbolAddress((void**)&ffw2R_, g_ffw2R);
    cudaGetSymbolAddress((void**)&woutR_, g_woutR);
    cudaGetSymbolAddress((void**)&wA_,    g_wA);
    cudaGetSymbolAddress((void**)&wB_,    g_wB);
    cudaGetSymbolAddress((void**)&wt_,    g_wt);

    // dynamic smem sizes
    const int smem_big   = 4 * (128 * 20 + 16 * 136) * 4;   // 75776 B
    const int smem_small = 4 * (64 * 20 + 16 * 136) * 4;    // 55296 B
    cudaFuncSetAttribute(tg<4, 0, false, false>,
        cudaFuncAttributeMaxDynamicSharedMemorySize, smem_big);
    cudaFuncSetAttribute(tg<4, 1, false, true>,
        cudaFuncAttributeMaxDynamicSharedMemorySize, smem_big);
    cudaFuncSetAttribute(tg<2, 0, false, false>,
        cudaFuncAttributeMaxDynamicSharedMemorySize, smem_small);
    cudaFuncSetAttribute(tg<2, 0, true, false>,
        cudaFuncAttributeMaxDynamicSharedMemorySize, smem_small);

    // Weight prep (rounded, [K][N] layouts)
    rcopy_kernel<<<(2 * ND * NFF / 4 + 255) / 256, 256>>>(wqkv, wqkvR_, 2 * ND * NFF / 4);
    rcopy_kernel<<<(2 * ND * NFF / 4 + 255) / 256, 256>>>(ffw1, ffw1R_, 2 * ND * NFF / 4);
    rcopy_kernel<<<(2 * NFF * ND / 4 + 255) / 256, 256>>>(ffw2, ffw2R_, 2 * NFF * ND / 4);
    rcopy_kernel<<<(2 * NINNER * ND / 4 + 255) / 256, 256>>>(wout, woutR_, 2 * NINNER * ND / 4);
    transpose_kernel<<<dim3(NC / 32, ND / 32), dim3(32, 8)>>>(proj_in_w, wA_, ND, NC);
    transpose_kernel<<<dim3(ND / 32, NC / 32), dim3(32, 8)>>>(proj_out_w, wB_, NC, ND);
    wtrans_kernel<<<(3 * ND * ND + 255) / 256, 256>>>(local_w, wt_);

    // 1. pool -> xpT (t1), rounded
    pool_kernel<<<NB * NC, 256>>>(x, t1_);
    // 2. h = xpT @ wA + proj_in_b   (M=4096, N=384, K=512)
    tg<2, 0, false, false><<<dim3(3, 64), 256, smem_small>>>(
        t1_, wA_, proj_in_b, nullptr, h_, NROWS, ND, NC);
    // 3. norm_in (in-place, NOT rounded - residual stream)
    ln_kernel<false><<<NROWS / 8, 256>>>(h_, norm_in_g, norm_in_b, h_);

    for (int i = 0; i < 2; i++) {
        ln_kernel<true><<<NROWS / 8, 256>>>(h_, ln1_g + i * ND, ln1_b + i * ND, t2_);
        tg<4, 0, false, false><<<dim3(12, 32), 256, smem_big>>>(
            t2_, wqkvR_ + (size_t)i * ND * NFF, nullptr, nullptr, y_, NROWS, NFF, ND);
        attn_kernel<<<NB * NHEADS, 256>>>(y_, rf + i * NDH * NDH, t1_);
        tg<2, 0, true, false><<<dim3(3, 64), 256, smem_small>>>(
            t1_, woutR_ + (size_t)i * NINNER * ND, bout + i * ND, h_, h_, NROWS, ND, NINNER);
        ln_kernel<true><<<NROWS / 8, 256>>>(h_, ln2_g + i * ND, ln2_b + i * ND, t2_);
        tg<4, 1, false, true><<<dim3(12, 32), 256, smem_big>>>(
            t2_, ffw1R_ + (size_t)i * ND * NFF, ffb1 + i * NFF, nullptr, y_, NROWS, NFF, ND);
        tg<2, 0, true, false><<<dim3(3, 64), 256, smem_small>>>(
            y_, ffw2R_ + (size_t)i * NFF * ND, ffb2 + i * ND, h_, h_, NROWS, ND, NFF);
    }

    // local conv as one GEMM: t3 = h + gather(h) @ wt + local_b
    gather_kernel<<<(NROWS * 288) / 256, 256>>>(h_, y_);
    tg<2, 0, true, false><<<dim3(3, 64), 256, smem_small>>>(
        y_, wt_, local_b, h_, t3_, NROWS, ND, 3 * ND);
    // norm_out (rounded - feeds proj_out GEMM)
    ln_kernel<true><<<NROWS / 8, 256>>>(t3_, norm_out_g, norm_out_b, h_);
    // hp = h @ wB + proj_out_b   (M=4096, N=512, K=384)
    tg<2, 0, false, false><<<dim3(4, 64), 256, smem_small>>>(
        h_, wB_, proj_out_b, nullptr, t1_, NROWS, NC, ND);
    // interp + residual with x
    final_kernel<<<(NB * NC * NL) / 256, 256>>>(t1_, x, out);
}

// round 8
// speedup vs baseline: 1.9512x; 1.9512x over previous
#include <cuda_runtime.h>
#include <cuda_fp16.h>
#include <cstdint>
#include <math.h>

// Problem constants
#define NB   16
#define NC   512
#define NL   4096
#define ND   384
#define NTOK 256
#define NROWS 4096      // NB*NTOK
#define NINNER 512
#define NFF  1536
#define NHEADS 8
#define NDH  64

// ---------------------------------------------------------------------------
// Scratch (device globals; allocation-free)
// ---------------------------------------------------------------------------
__device__ alignas(16) float  g_h  [NROWS*ND];      // residual stream (fp32)
__device__ alignas(16) float  g_t3 [NROWS*ND];      // conv out (fp32)
__device__ alignas(16) float  g_hp [NROWS*NC];      // hp for final (fp32)
__device__ alignas(16) __half g_xp [NROWS*NINNER];  // pool out / attn out (half)
__device__ alignas(16) __half g_t2h[NROWS*ND];      // LN outputs (half)
__device__ alignas(16) __half g_yh [NROWS*NFF];     // qkv / ff1 / gather (half)
// half weights
__device__ alignas(16) __half g_wqkvH[2*ND*NFF];    // [K=384][N=1536]
__device__ alignas(16) __half g_ffw1H[2*ND*NFF];    // [K=384][N=1536]
__device__ alignas(16) __half g_ffw2H[2*NFF*ND];    // [K=1536][N=384]
__device__ alignas(16) __half g_woutH[2*NINNER*ND]; // [K=512][N=384]
__device__ alignas(16) __half g_wAH[NC*ND];         // proj_in^T  [512][384]
__device__ alignas(16) __half g_wBH[ND*NC];         // proj_out^T [384][512]
__device__ alignas(16) __half g_wtH[3*ND*ND];       // conv [K=1152][N=384]

__device__ __forceinline__ float gelu_exact(float v) { return v * normcdff(v); }

__device__ __forceinline__ float4 ld4h(const __half* p) {
    uint2 u = *(const uint2*)p;
    float2 fa = __half22float2(*(__half2*)&u.x);
    float2 fb = __half22float2(*(__half2*)&u.y);
    return make_float4(fa.x, fa.y, fb.x, fb.y);
}
__device__ __forceinline__ void st4h(__half* p, float4 v) {
    uint2 u;
    *(__half2*)&u.x = __floats2half2_rn(v.x, v.y);
    *(__half2*)&u.y = __floats2half2_rn(v.z, v.w);
    *(uint2*)p = u;
}

__device__ __forceinline__ void mma_f16(float (&d)[4], const unsigned (&a)[4],
                                        const unsigned (&b)[2]) {
    asm volatile(
        "mma.sync.aligned.m16n8k16.row.col.f32.f16.f16.f32 "
        "{%0,%1,%2,%3}, {%4,%5,%6,%7}, {%8,%9}, {%0,%1,%2,%3};\n"
        : "+f"(d[0]), "+f"(d[1]), "+f"(d[2]), "+f"(d[3])
        : "r"(a[0]), "r"(a[1]), "r"(a[2]), "r"(a[3]), "r"(b[0]), "r"(b[1]));
}

__device__ __forceinline__ void ldsm4(unsigned (&r)[4], uint32_t addr) {
    asm volatile("ldmatrix.sync.aligned.m8n8.x4.shared.b16 {%0,%1,%2,%3}, [%4];"
                 : "=r"(r[0]), "=r"(r[1]), "=r"(r[2]), "=r"(r[3]) : "r"(addr));
}
__device__ __forceinline__ void ldsm4t(unsigned& r0, unsigned& r1,
                                       unsigned& r2, unsigned& r3, uint32_t addr) {
    asm volatile("ldmatrix.sync.aligned.m8n8.x4.trans.shared.b16 {%0,%1,%2,%3}, [%4];"
                 : "=r"(r0), "=r"(r1), "=r"(r2), "=r"(r3) : "r"(addr));
}

// ---------------------------------------------------------------------------
// fp16 mma.sync GEMM, register-staged double buffer, ldmatrix fragments.
// BM = MT*32, BN=128, BK=32. 128 threads = 4 warps (2x2); warp tile (MT*16)x64.
// LDA=40 halves (80B rows): 16B-aligned stores, conflict-free ldmatrix (5i mod 8).
// LDB=136 halves (272B rows): 16B-aligned, conflict-free (17i mod 8).
// OUTH=1: write __half output; else fp32. ACC adds fp32 Cin. ACT=1: exact GELU.
// ---------------------------------------------------------------------------
template<int MT, int ACT, bool ACC, int OUTH>
__global__ __launch_bounds__(128, 2) void hgemm(
    const __half* __restrict__ A, const __half* __restrict__ Bw,
    const float* __restrict__ bias, const float* __restrict__ Cin,
    void* __restrict__ Cv, int M, int N, int K)
{
    constexpr int BM  = MT * 32;
    constexpr int LDA = 40;              // halves (80B rows)
    constexpr int LDB = 136;             // halves (272B rows)
    constexpr int ALD = BM / 32;         // A 16B-chunks per thread

    __shared__ alignas(16) __half As[2][BM * LDA];
    __shared__ alignas(16) __half Bs[2][32 * LDB];

    const int tid = threadIdx.x;
    const int warp = tid >> 5, lane = tid & 31;
    const int wr = warp >> 1, wc = warp & 1;
    const int wm = wr * (MT * 16), wn = wc * 64;
    const int m0 = blockIdx.y * BM, n0 = blockIdx.x * 128;
    const int NS = K >> 5;

    float acc[MT][8][4];
#pragma unroll
    for (int mt = 0; mt < MT; mt++)
#pragma unroll
        for (int nt = 0; nt < 8; nt++)
#pragma unroll
            for (int i = 0; i < 4; i++) acc[mt][nt][i] = 0.f;

    uint4 stA[ALD], stB[4];

    auto loadA = [&](int s) {
#pragma unroll
        for (int i = 0; i < ALD; i++) {
            int lin = tid + i * 128;
            int row = lin >> 2, ch = lin & 3;
            stA[i] = *(const uint4*)(A + (size_t)(m0 + row) * K + s * 32 + ch * 8);
        }
    };
    auto loadB = [&](int s) {
#pragma unroll
        for (int i = 0; i < 4; i++) {
            int lin = tid + i * 128;
            int row = lin >> 4, c8 = (lin & 15) << 3;
            stB[i] = *(const uint4*)(Bw + (size_t)(s * 32 + row) * N + n0 + c8);
        }
    };

    loadA(0); loadB(0);

    for (int s = 0; s < NS; s++) {
        const int buf = s & 1;
#pragma unroll
        for (int i = 0; i < ALD; i++) {
            int lin = tid + i * 128;
            int row = lin >> 2, ch = lin & 3;
            *(uint4*)&As[buf][row * LDA + ch * 8] = stA[i];
        }
#pragma unroll
        for (int i = 0; i < 4; i++) {
            int lin = tid + i * 128;
            int row = lin >> 4, c8 = (lin & 15) << 3;
            *(uint4*)&Bs[buf][row * LDB + c8] = stB[i];
        }
        __syncthreads();

        if (s + 1 < NS) { loadA(s + 1); loadB(s + 1); }

#pragma unroll
        for (int ks = 0; ks < 2; ks++) {
            unsigned af[MT][4], bf[8][2];
#pragma unroll
            for (int mt = 0; mt < MT; mt++) {
                uint32_t a = (uint32_t)__cvta_generic_to_shared(
                    &As[buf][(wm + mt * 16 + (lane & 15)) * LDA + ks * 16 + ((lane >> 4) << 3)]);
                ldsm4(af[mt], a);
            }
#pragma unroll
            for (int np = 0; np < 4; np++) {
                uint32_t a = (uint32_t)__cvta_generic_to_shared(
                    &Bs[buf][(ks * 16 + (lane & 15)) * LDB + wn + np * 16 + ((lane >> 4) << 3)]);
                ldsm4t(bf[np * 2][0], bf[np * 2][1], bf[np * 2 + 1][0], bf[np * 2 + 1][1], a);
            }
#pragma unroll
            for (int mt = 0; mt < MT; mt++)
#pragma unroll
                for (int nt = 0; nt < 8; nt++)
                    mma_f16(acc[mt][nt], af[mt], bf[nt]);
        }
    }

    // epilogue
#pragma unroll
    for (int mt = 0; mt < MT; mt++) {
#pragma unroll
        for (int nt = 0; nt < 8; nt++) {
#pragma unroll
            for (int half_i = 0; half_i < 2; half_i++) {
                const int row = m0 + wm + mt * 16 + (lane >> 2) + half_i * 8;
                const int col = n0 + wn + nt * 8 + (lane & 3) * 2;
                float2 r;
                r.x = acc[mt][nt][half_i * 2];
                r.y = acc[mt][nt][half_i * 2 + 1];
                if (bias) { r.x += bias[col]; r.y += bias[col + 1]; }
                if (ACT == 1) { r.x = gelu_exact(r.x); r.y = gelu_exact(r.y); }
                if (ACC) {
                    const float* cp = Cin + (size_t)row * N + col;
                    r.x += cp[0]; r.y += cp[1];
                }
                if (OUTH) {
                    __half2* cp = (__half2*)((__half*)Cv + (size_t)row * N + col);
                    *cp = __floats2half2_rn(r.x, r.y);
                } else {
                    *(float2*)((float*)Cv + (size_t)row * N + col) = r;
                }
            }
        }
    }
}

// ---------------------------------------------------------------------------
// Weight conversion kernels
// ---------------------------------------------------------------------------
__global__ __launch_bounds__(256) void hcopy_kernel(const float* __restrict__ in,
                                                    __half* __restrict__ out, int n4)
{
    int i = blockIdx.x * 256 + threadIdx.x;
    if (i >= n4) return;
    st4h(out + (size_t)i * 4, ((const float4*)in)[i]);
}

__global__ __launch_bounds__(256) void htranspose_kernel(const float* __restrict__ src,
                                                         __half* __restrict__ dst,
                                                         int R, int Cc)
{
    __shared__ float t[32][33];
    int c = blockIdx.x * 32 + threadIdx.x;
    int r = blockIdx.y * 32 + threadIdx.y;
#pragma unroll
    for (int i = 0; i < 32; i += 8)
        t[threadIdx.y + i][threadIdx.x] = src[(size_t)(r + i) * Cc + c];
    __syncthreads();
    int co = blockIdx.y * 32 + threadIdx.x;
    int ro = blockIdx.x * 32 + threadIdx.y;
#pragma unroll
    for (int i = 0; i < 32; i += 8)
        dst[(size_t)(ro + i) * R + co] = __float2half(t[threadIdx.x][threadIdx.y + i]);
}

// conv weight: lw[dout,din,k] -> wt[(k*384+din)][dout]
__global__ __launch_bounds__(256) void hwtrans_kernel(const float* __restrict__ lw,
                                                      __half* __restrict__ wt)
{
    int idx = blockIdx.x * 256 + threadIdx.x;
    if (idx >= 3 * ND * ND) return;
    int krow = idx / ND;
    int dout = idx - krow * ND;
    int k = krow / ND, din = krow - k * ND;
    wt[idx] = __float2half(lw[(dout * ND + din) * 3 + k]);
}

// ---------------------------------------------------------------------------
// Pool: x[B,C,L] -> xpT[(b*256+n), c] (half), mean over windows of 16
// ---------------------------------------------------------------------------
__global__ __launch_bounds__(256) void pool_kernel(const float* __restrict__ x,
                                                   __half* __restrict__ xpT)
{
    int bc = blockIdx.x;
    int b = bc >> 9, c = bc & 511;
    const float4* src = (const float4*)(x + (size_t)bc * NL) + threadIdx.x * 4;
    float s = 0.f;
#pragma unroll
    for (int j = 0; j < 4; j++) {
        float4 v = src[j];
        s += v.x + v.y + v.z + v.w;
    }
    xpT[((size_t)(b * NTOK + threadIdx.x)) * NC + c] = __float2half(s * (1.f / 16.f));
}

// ---------------------------------------------------------------------------
// LayerNorm over last dim (384). Warp per row. OUTH: half output.
// ---------------------------------------------------------------------------
template<int OUTH>
__global__ __launch_bounds__(256) void ln_kernel(const float* __restrict__ in,
                                                 const float* __restrict__ g,
                                                 const float* __restrict__ b,
                                                 void* __restrict__ outv)
{
    const int wid = threadIdx.x >> 5, lane = threadIdx.x & 31;
    const int row = blockIdx.x * 8 + wid;
    const float* xr = in + (size_t)row * ND;
    float4 v0 = *(const float4*)(xr + lane * 4);
    float4 v1 = *(const float4*)(xr + 128 + lane * 4);
    float4 v2 = *(const float4*)(xr + 256 + lane * 4);
    float s = v0.x + v0.y + v0.z + v0.w + v1.x + v1.y + v1.z + v1.w
            + v2.x + v2.y + v2.z + v2.w;
    float q = v0.x*v0.x + v0.y*v0.y + v0.z*v0.z + v0.w*v0.w
            + v1.x*v1.x + v1.y*v1.y + v1.z*v1.z + v1.w*v1.w
            + v2.x*v2.x + v2.y*v2.y + v2.z*v2.z + v2.w*v2.w;
#pragma unroll
    for (int o = 16; o; o >>= 1) {
        s += __shfl_xor_sync(0xFFFFFFFFu, s, o);
        q += __shfl_xor_sync(0xFFFFFFFFu, q, o);
    }
    const float mean = s * (1.f / ND);
    const float var  = q * (1.f / ND) - mean * mean;
    const float inv  = rsqrtf(var + 1e-5f);
#pragma unroll
    for (int j = 0; j < 3; j++) {
        int col = j * 128 + lane * 4;
        float4 v = (j == 0) ? v0 : (j == 1) ? v1 : v2;
        float4 gg = *(const float4*)(g + col);
        float4 bb = *(const float4*)(b + col);
        float4 r;
        r.x = (v.x - mean) * inv * gg.x + bb.x;
        r.y = (v.y - mean) * inv * gg.y + bb.y;
        r.z = (v.z - mean) * inv * gg.z + bb.z;
        r.w = (v.w - mean) * inv * gg.w + bb.w;
        if (OUTH) st4h((__half*)outv + (size_t)row * ND + col, r);
        else      *(float4*)((float*)outv + (size_t)row * ND + col) = r;
    }
}

// ---------------------------------------------------------------------------
// Linear attention per (b,h); half in (qkv), half out. Internal fp32.
// ---------------------------------------------------------------------------
__device__ __forceinline__ void r1u(float (&acc)[4][4], float a0, float a1,
                                    float a2, float a3, const float4 b)
{
    acc[0][0] += a0 * b.x; acc[0][1] += a0 * b.y; acc[0][2] += a0 * b.z; acc[0][3] += a0 * b.w;
    acc[1][0] += a1 * b.x; acc[1][1] += a1 * b.y; acc[1][2] += a1 * b.z; acc[1][3] += a1 * b.w;
    acc[2][0] += a2 * b.x; acc[2][1] += a2 * b.y; acc[2][2] += a2 * b.z; acc[2][3] += a2 * b.w;
    acc[3][0] += a3 * b.x; acc[3][1] += a3 * b.y; acc[3][2] += a3 * b.z; acc[3][3] += a3 * b.w;
}

__global__ __launch_bounds__(256) void attn_kernel(const __half* __restrict__ qkv,
                                                   const float* __restrict__ rf,
                                                   __half* __restrict__ o)
{
    __shared__ float rf_s[4096];
    __shared__ float bufA[4096];
    __shared__ float bufB[4096];
    const int tid = threadIdx.x;
    const int bh = blockIdx.x;
    const int b = bh >> 3, h = bh & 7;
    const int tq = tid >> 4, tr = tid & 15;

#pragma unroll
    for (int j = 0; j < 4; j++)
        ((float4*)rf_s)[tid + j * 256] = ((const float4*)rf)[tid + j * 256];

    const __half* base = qkv + (size_t)b * NTOK * NFF + h * NDH;

    float kv[4][4];
#pragma unroll
    for (int i = 0; i < 4; i++)
#pragma unroll
        for (int j = 0; j < 4; j++) kv[i][j] = 0.f;

    for (int n0 = 0; n0 < NTOK; n0 += 64) {
        __syncthreads();
#pragma unroll
        for (int j = 0; j < 4; j++) {
            int lin = tid + j * 256;
            int rowi = lin >> 4, c4 = (lin & 15) << 2;
            const __half* rp = base + (size_t)(n0 + rowi) * NFF;
            float4 kk = ld4h(rp + NINNER + c4);
            kk.x = fmaxf(kk.x, 0.f); kk.y = fmaxf(kk.y, 0.f);
            kk.z = fmaxf(kk.z, 0.f); kk.w = fmaxf(kk.w, 0.f);
            *(float4*)&bufA[rowi * 64 + c4] = kk;
            *(float4*)&bufB[rowi * 64 + c4] = ld4h(rp + 2 * NINNER + c4);
        }
        __syncthreads();
#pragma unroll 8
        for (int nn = 0; nn < 64; nn++) {
            float4 ka = *(const float4*)&bufA[nn * 64 + tq * 4];
            float4 vb = *(const float4*)&bufB[nn * 64 + tr * 4];
            r1u(kv, ka.x, ka.y, ka.z, ka.w, vb);
        }
    }
    __syncthreads();
#pragma unroll
    for (int i = 0; i < 4; i++) {
        float4 v = make_float4(kv[i][0], kv[i][1], kv[i][2], kv[i][3]);
        *(float4*)&bufA[(tq * 4 + i) * 64 + tr * 4] = v;
    }
    __syncthreads();

    float w1[4][4];
#pragma unroll
    for (int i = 0; i < 4; i++)
#pragma unroll
        for (int j = 0; j < 4; j++) w1[i][j] = 0.f;
#pragma unroll 8
    for (int dk = 0; dk < 64; dk++) {
        float4 rm = *(const float4*)&rf_s[dk * 64 + tq * 4];
        float4 kd = *(const float4*)&bufA[dk * 64 + tr * 4];
        r1u(w1, rm.x, rm.y, rm.z, rm.w, kd);
    }
    __syncthreads();
#pragma unroll
    for (int i = 0; i < 4; i++) {
        float4 v = make_float4(w1[i][0], w1[i][1], w1[i][2], w1[i][3]);
        *(float4*)&bufB[(tq * 4 + i) * 64 + tr * 4] = v;
    }
    __syncthreads();

    float w2[4][4];
#pragma unroll
    for (int i = 0; i < 4; i++)
#pragma unroll
        for (int j = 0; j < 4; j++) w2[i][j] = 0.f;
#pragma unroll 8
    for (int m = 0; m < 64; m++) {
        float4 wd = *(const float4*)&bufB[m * 64 + tr * 4];
        float r0 = rf_s[(tq * 4 + 0) * 64 + m];
        float r1 = rf_s[(tq * 4 + 1) * 64 + m];
        float r2 = rf_s[(tq * 4 + 2) * 64 + m];
        float r3 = rf_s[(tq * 4 + 3) * 64 + m];
        r1u(w2, r0, r1, r2, r3, wd);
    }
    __syncthreads();
#pragma unroll
    for (int i = 0; i < 4; i++) {
        float4 v = make_float4(w2[i][0], w2[i][1], w2[i][2], w2[i][3]);
        *(float4*)&bufA[(tq * 4 + i) * 64 + tr * 4] = v;
    }
    __syncthreads();

    for (int n0 = 0; n0 < NTOK; n0 += 64) {
#pragma unroll
        for (int j = 0; j < 4; j++) {
            int lin = tid + j * 256;
            int rowi = lin >> 4, c4 = (lin & 15) << 2;
            const __half* rp = base + (size_t)(n0 + rowi) * NFF;
            float4 qq = ld4h(rp + c4);
            qq.x = fmaxf(qq.x, 0.f) * 0.125f; qq.y = fmaxf(qq.y, 0.f) * 0.125f;
            qq.z = fmaxf(qq.z, 0.f) * 0.125f; qq.w = fmaxf(qq.w, 0.f) * 0.125f;
            *(float4*)&bufB[rowi * 64 + c4] = qq;
        }
        __syncthreads();
        float oc[4][4];
#pragma unroll
        for (int i = 0; i < 4; i++)
#pragma unroll
            for (int j = 0; j < 4; j++) oc[i][j] = 0.f;
#pragma unroll 8
        for (int dq = 0; dq < 64; dq++) {
            float4 wd = *(const float4*)&bufA[dq * 64 + tr * 4];
            float q0 = bufB[(tq * 4 + 0) * 64 + dq];
            float q1 = bufB[(tq * 4 + 1) * 64 + dq];
            float q2 = bufB[(tq * 4 + 2) * 64 + dq];
            float q3 = bufB[(tq * 4 + 3) * 64 + dq];
            r1u(oc, q0, q1, q2, q3, wd);
        }
#pragma unroll
        for (int i = 0; i < 4; i++) {
            st4h(o + (size_t)(b * NTOK + n0 + tq * 4 + i) * NINNER + h * NDH + tr * 4,
                 make_float4(oc[i][0], oc[i][1], oc[i][2], oc[i][3]));
        }
        __syncthreads();
    }
}

// ---------------------------------------------------------------------------
// Conv gather (half out): A_ext[r] = [h[r-1] | h[r] | h[r+1]], batch-edge zeros
// ---------------------------------------------------------------------------
__global__ __launch_bounds__(256) void gather_kernel(const float* __restrict__ h,
                                                     __half* __restrict__ aext)
{
    int idx = blockIdx.x * 256 + threadIdx.x;   // 4-elem group index
    int r = idx / 288;
    int c4 = idx - r * 288;
    int seg = c4 / 96;
    int col = (c4 - seg * 96) * 4;
    int n = r & 255;
    int src = r + seg - 1;
    float4 v = make_float4(0.f, 0.f, 0.f, 0.f);
    bool ok = (seg == 1) || (seg == 0 && n > 0) || (seg == 2 && n < 255);
    if (ok) v = *(const float4*)(h + (size_t)src * ND + col);
    st4h(aext + (size_t)r * 1152 + c4 * 4, v);
}

// ---------------------------------------------------------------------------
// Final: out[b,c,l] = interp(hp)[b,c,l] + x[b,c,l]
// ---------------------------------------------------------------------------
__global__ __launch_bounds__(256) void final_kernel(const float* __restrict__ hp,
                                                    const float* __restrict__ x,
                                                    float* __restrict__ out)
{
    size_t idx = (size_t)blockIdx.x * 256 + threadIdx.x;
    int l = (int)(idx & 4095);
    int c = (int)((idx >> 12) & 511);
    int b = (int)(idx >> 21);
    float src = fmaxf((l + 0.5f) * 0.0625f - 0.5f, 0.f);
    int i0 = (int)src;
    float w = src - (float)i0;
    int i1 = min(i0 + 1, 255);
    float v0 = hp[(size_t)(b * NTOK + i0) * NC + c];
    float v1 = hp[(size_t)(b * NTOK + i1) * NC + c];
    out[idx] = v0 * (1.f - w) + v1 * w + x[idx];
}

// ---------------------------------------------------------------------------
// Host orchestration
// ---------------------------------------------------------------------------
extern "C" void kernel_launch(void* const* d_in, const int* in_sizes, int n_in,
                              void* d_out, int out_size)
{
    const float* x          = (const float*)d_in[0];
    const float* proj_in_w  = (const float*)d_in[1];
    const float* proj_in_b  = (const float*)d_in[2];
    const float* norm_in_g  = (const float*)d_in[3];
    const float* norm_in_b  = (const float*)d_in[4];
    const float* ln1_g      = (const float*)d_in[5];
    const float* ln1_b      = (const float*)d_in[6];
    const float* wqkv       = (const float*)d_in[7];
    const float* rf         = (const float*)d_in[8];
    const float* wout       = (const float*)d_in[9];
    const float* bout       = (const float*)d_in[10];
    const float* ln2_g      = (const float*)d_in[11];
    const float* ln2_b      = (const float*)d_in[12];
    const float* ffw1       = (const float*)d_in[13];
    const float* ffb1       = (const float*)d_in[14];
    const float* ffw2       = (const float*)d_in[15];
    const float* ffb2       = (const float*)d_in[16];
    const float* local_w    = (const float*)d_in[17];
    const float* local_b    = (const float*)d_in[18];
    const float* norm_out_g = (const float*)d_in[19];
    const float* norm_out_b = (const float*)d_in[20];
    const float* proj_out_w = (const float*)d_in[21];
    const float* proj_out_b = (const float*)d_in[22];
    float* out = (float*)d_out;

    float *h_, *t3_, *hp_;
    __half *xp_, *t2h_, *yh_;
    __half *wqkvH_, *ffw1H_, *ffw2H_, *woutH_, *wAH_, *wBH_, *wtH_;
    cudaGetSymbolAddress((void**)&h_,     g_h);
    cudaGetSymbolAddress((void**)&t3_,    g_t3);
    cudaGetSymbolAddress((void**)&hp_,    g_hp);
    cudaGetSymbolAddress((void**)&xp_,    g_xp);
    cudaGetSymbolAddress((void**)&t2h_,   g_t2h);
    cudaGetSymbolAddress((void**)&yh_,    g_yh);
    cudaGetSymbolAddress((void**)&wqkvH_, g_wqkvH);
    cudaGetSymbolAddress((void**)&ffw1H_, g_ffw1H);
    cudaGetSymbolAddress((void**)&ffw2H_, g_ffw2H);
    cudaGetSymbolAddress((void**)&woutH_, g_woutH);
    cudaGetSymbolAddress((void**)&wAH_,   g_wAH);
    cudaGetSymbolAddress((void**)&wBH_,   g_wBH);
    cudaGetSymbolAddress((void**)&wtH_,   g_wtH);

    // Weight prep (half, [K][N] layouts)
    hcopy_kernel<<<(2 * ND * NFF / 4 + 255) / 256, 256>>>(wqkv, wqkvH_, 2 * ND * NFF / 4);
    hcopy_kernel<<<(2 * ND * NFF / 4 + 255) / 256, 256>>>(ffw1, ffw1H_, 2 * ND * NFF / 4);
    hcopy_kernel<<<(2 * NFF * ND / 4 + 255) / 256, 256>>>(ffw2, ffw2H_, 2 * NFF * ND / 4);
    hcopy_kernel<<<(2 * NINNER * ND / 4 + 255) / 256, 256>>>(wout, woutH_, 2 * NINNER * ND / 4);
    htranspose_kernel<<<dim3(NC / 32, ND / 32), dim3(32, 8)>>>(proj_in_w, wAH_, ND, NC);
    htranspose_kernel<<<dim3(ND / 32, NC / 32), dim3(32, 8)>>>(proj_out_w, wBH_, NC, ND);
    hwtrans_kernel<<<(3 * ND * ND + 255) / 256, 256>>>(local_w, wtH_);

    // 1. pool -> xp (half)
    pool_kernel<<<NB * NC, 256>>>(x, xp_);
    // 2. h = xp @ wAH + proj_in_b   (M=4096, N=384, K=512) -> fp32
    hgemm<2, 0, false, 0><<<dim3(3, 64), 128>>>(
        xp_, wAH_, proj_in_b, nullptr, h_, NROWS, ND, NC);
    // 3. norm_in (fp32 residual)
    ln_kernel<0><<<NROWS / 8, 256>>>(h_, norm_in_g, norm_in_b, h_);

    for (int i = 0; i < 2; i++) {
        ln_kernel<1><<<NROWS / 8, 256>>>(h_, ln1_g + i * ND, ln1_b + i * ND, t2h_);
        hgemm<4, 0, false, 1><<<dim3(12, 32), 128>>>(
            t2h_, wqkvH_ + (size_t)i * ND * NFF, nullptr, nullptr, yh_, NROWS, NFF, ND);
        attn_kernel<<<NB * NHEADS, 256>>>(yh_, rf + i * NDH * NDH, xp_);
        hgemm<2, 0, true, 0><<<dim3(3, 64), 128>>>(
            xp_, woutH_ + (size_t)i * NINNER * ND, bout + i * ND, h_, h_, NROWS, ND, NINNER);
        ln_kernel<1><<<NROWS / 8, 256>>>(h_, ln2_g + i * ND, ln2_b + i * ND, t2h_);
        hgemm<4, 1, false, 1><<<dim3(12, 32), 128>>>(
            t2h_, ffw1H_ + (size_t)i * ND * NFF, ffb1 + i * NFF, nullptr, yh_, NROWS, NFF, ND);
        hgemm<2, 0, true, 0><<<dim3(3, 64), 128>>>(
            yh_, ffw2H_ + (size_t)i * NFF * ND, ffb2 + i * ND, h_, h_, NROWS, ND, NFF);
    }

    // local conv as one GEMM: t3 = h + gather(h) @ wtH + local_b
    gather_kernel<<<(NROWS * 288) / 256, 256>>>(h_, yh_);
    hgemm<2, 0, true, 0><<<dim3(3, 64), 128>>>(
        yh_, wtH_, local_b, h_, t3_, NROWS, ND, 3 * ND);
    // norm_out -> half (feeds proj_out)
    ln_kernel<1><<<NROWS / 8, 256>>>(t3_, norm_out_g, norm_out_b, t2h_);
    // hp = t2h @ wBH + proj_out_b   (M=4096, N=512, K=384) -> fp32
    hgemm<2, 0, false, 0><<<dim3(4, 64), 128>>>(
        t2h_, wBH_, proj_out_b, nullptr, hp_, NROWS, NC, ND);
    // interp + residual with x
    final_kernel<<<(NB * NC * NL) / 256, 256>>>(hp_, x, out);
}

// round 9
// speedup vs baseline: 2.1354x; 1.0944x over previous
#include <cuda_runtime.h>
#include <cuda_fp16.h>
#include <cstdint>
#include <math.h>

// Problem constants
#define NB   16
#define NC   512
#define NL   4096
#define ND   384
#define NTOK 256
#define NROWS 4096      // NB*NTOK
#define NINNER 512
#define NFF  1536
#define NHEADS 8
#define NDH  64

// ---------------------------------------------------------------------------
// Scratch (device globals; allocation-free)
// ---------------------------------------------------------------------------
__device__ alignas(16) float  g_h  [NROWS*ND];      // residual stream (fp32)
__device__ alignas(16) float  g_t3 [NROWS*ND];      // conv out (fp32)
__device__ alignas(16) float  g_hp [NROWS*NC];      // hp for final (fp32)
__device__ alignas(16) __half g_xp [NROWS*NINNER];  // pool out / attn out (half)
__device__ alignas(16) __half g_t2h[NROWS*ND];      // LN outputs (half)
__device__ alignas(16) __half g_yh [NROWS*NFF];     // qkv / ff1 / gather (half)
// half weights
__device__ alignas(16) __half g_wqkvH[2*ND*NFF];    // [K=384][N=1536]
__device__ alignas(16) __half g_ffw1H[2*ND*NFF];    // [K=384][N=1536]
__device__ alignas(16) __half g_ffw2H[2*NFF*ND];    // [K=1536][N=384]
__device__ alignas(16) __half g_woutH[2*NINNER*ND]; // [K=512][N=384]
__device__ alignas(16) __half g_wAH[NC*ND];         // proj_in^T  [512][384]
__device__ alignas(16) __half g_wBH[ND*NC];         // proj_out^T [384][512]
__device__ alignas(16) __half g_wtH[3*ND*ND];       // conv [K=1152][N=384]

__device__ __forceinline__ float gelu_exact(float v) { return v * normcdff(v); }

__device__ __forceinline__ float4 ld4h(const __half* p) {
    uint2 u = *(const uint2*)p;
    float2 fa = __half22float2(*(__half2*)&u.x);
    float2 fb = __half22float2(*(__half2*)&u.y);
    return make_float4(fa.x, fa.y, fb.x, fb.y);
}
__device__ __forceinline__ void st4h(__half* p, float4 v) {
    uint2 u;
    *(__half2*)&u.x = __floats2half2_rn(v.x, v.y);
    *(__half2*)&u.y = __floats2half2_rn(v.z, v.w);
    *(uint2*)p = u;
}

__device__ __forceinline__ void mma_f16(float (&d)[4], const unsigned (&a)[4],
                                        const unsigned (&b)[2]) {
    asm volatile(
        "mma.sync.aligned.m16n8k16.row.col.f32.f16.f16.f32 "
        "{%0,%1,%2,%3}, {%4,%5,%6,%7}, {%8,%9}, {%0,%1,%2,%3};\n"
        : "+f"(d[0]), "+f"(d[1]), "+f"(d[2]), "+f"(d[3])
        : "r"(a[0]), "r"(a[1]), "r"(a[2]), "r"(a[3]), "r"(b[0]), "r"(b[1]));
}

__device__ __forceinline__ void ldsm4(unsigned (&r)[4], uint32_t addr) {
    asm volatile("ldmatrix.sync.aligned.m8n8.x4.shared.b16 {%0,%1,%2,%3}, [%4];"
                 : "=r"(r[0]), "=r"(r[1]), "=r"(r[2]), "=r"(r[3]) : "r"(addr));
}
__device__ __forceinline__ void ldsm4t(unsigned& r0, unsigned& r1,
                                       unsigned& r2, unsigned& r3, uint32_t addr) {
    asm volatile("ldmatrix.sync.aligned.m8n8.x4.trans.shared.b16 {%0,%1,%2,%3}, [%4];"
                 : "=r"(r0), "=r"(r1), "=r"(r2), "=r"(r3) : "r"(addr));
}

// ---------------------------------------------------------------------------
// fp16 mma.sync GEMM, 256 threads (8 warps, 4x2), register-staged double buffer.
// BM = MT*64, BN=128, BK=32. Warp tile (MT*16)x64.
// LDA=40 halves (80B rows), LDB=136 halves (272B rows): 16B-aligned,
// conflict-free ldmatrix (5i mod 8 / 17i mod 8 distinct).
// OUTH=1: half output; else fp32. ACC adds fp32 Cin. ACT=1: exact GELU.
// ---------------------------------------------------------------------------
template<int MT, int ACT, bool ACC, int OUTH>
__global__ __launch_bounds__(256, 2) void hgemm(
    const __half* __restrict__ A, const __half* __restrict__ Bw,
    const float* __restrict__ bias, const float* __restrict__ Cin,
    void* __restrict__ Cv, int M, int N, int K)
{
    constexpr int BM  = MT * 64;
    constexpr int LDA = 40;
    constexpr int LDB = 136;

    __shared__ alignas(16) __half As[2][BM * LDA];
    __shared__ alignas(16) __half Bs[2][32 * LDB];

    const int tid = threadIdx.x;
    const int warp = tid >> 5, lane = tid & 31;
    const int wr = warp >> 1, wc = warp & 1;      // 4 x 2 warps
    const int wm = wr * (MT * 16), wn = wc * 64;
    const int m0 = blockIdx.y * BM, n0 = blockIdx.x * 128;
    const int NS = K >> 5;

    float acc[MT][8][4];
#pragma unroll
    for (int mt = 0; mt < MT; mt++)
#pragma unroll
        for (int nt = 0; nt < 8; nt++)
#pragma unroll
            for (int i = 0; i < 4; i++) acc[mt][nt][i] = 0.f;

    uint4 stA[MT], stB[2];

    auto loadA = [&](int s) {
#pragma unroll
        for (int i = 0; i < MT; i++) {
            int lin = tid + i * 256;
            int row = lin >> 2, ch = lin & 3;     // 4 x 16B chunks per 32-half row
            stA[i] = *(const uint4*)(A + (size_t)(m0 + row) * K + s * 32 + ch * 8);
        }
    };
    auto loadB = [&](int s) {
#pragma unroll
        for (int i = 0; i < 2; i++) {
            int lin = tid + i * 256;
            int row = lin >> 4, c8 = (lin & 15) << 3;
            stB[i] = *(const uint4*)(Bw + (size_t)(s * 32 + row) * N + n0 + c8);
        }
    };

    loadA(0); loadB(0);

    for (int s = 0; s < NS; s++) {
        const int buf = s & 1;
#pragma unroll
        for (int i = 0; i < MT; i++) {
            int lin = tid + i * 256;
            int row = lin >> 2, ch = lin & 3;
            *(uint4*)&As[buf][row * LDA + ch * 8] = stA[i];
        }
#pragma unroll
        for (int i = 0; i < 2; i++) {
            int lin = tid + i * 256;
            int row = lin >> 4, c8 = (lin & 15) << 3;
            *(uint4*)&Bs[buf][row * LDB + c8] = stB[i];
        }
        __syncthreads();

        if (s + 1 < NS) { loadA(s + 1); loadB(s + 1); }

#pragma unroll
        for (int ks = 0; ks < 2; ks++) {
            unsigned af[MT][4], bf[8][2];
#pragma unroll
            for (int mt = 0; mt < MT; mt++) {
                uint32_t a = (uint32_t)__cvta_generic_to_shared(
                    &As[buf][(wm + mt * 16 + (lane & 15)) * LDA + ks * 16 + ((lane >> 4) << 3)]);
                ldsm4(af[mt], a);
            }
#pragma unroll
            for (int np = 0; np < 4; np++) {
                uint32_t a = (uint32_t)__cvta_generic_to_shared(
                    &Bs[buf][(ks * 16 + (lane & 15)) * LDB + wn + np * 16 + ((lane >> 4) << 3)]);
                ldsm4t(bf[np * 2][0], bf[np * 2][1], bf[np * 2 + 1][0], bf[np * 2 + 1][1], a);
            }
#pragma unroll
            for (int mt = 0; mt < MT; mt++)
#pragma unroll
                for (int nt = 0; nt < 8; nt++)
                    mma_f16(acc[mt][nt], af[mt], bf[nt]);
        }
        __syncthreads();
    }

    // epilogue
#pragma unroll
    for (int mt = 0; mt < MT; mt++) {
#pragma unroll
        for (int nt = 0; nt < 8; nt++) {
#pragma unroll
            for (int half_i = 0; half_i < 2; half_i++) {
                const int row = m0 + wm + mt * 16 + (lane >> 2) + half_i * 8;
                const int col = n0 + wn + nt * 8 + (lane & 3) * 2;
                float2 r;
                r.x = acc[mt][nt][half_i * 2];
                r.y = acc[mt][nt][half_i * 2 + 1];
                if (bias) { r.x += bias[col]; r.y += bias[col + 1]; }
                if (ACT == 1) { r.x = gelu_exact(r.x); r.y = gelu_exact(r.y); }
                if (ACC) {
                    const float* cp = Cin + (size_t)row * N + col;
                    r.x += cp[0]; r.y += cp[1];
                }
                if (OUTH) {
                    __half2* cp = (__half2*)((__half*)Cv + (size_t)row * N + col);
                    *cp = __floats2half2_rn(r.x, r.y);
                } else {
                    *(float2*)((float*)Cv + (size_t)row * N + col) = r;
                }
            }
        }
    }
}

// ---------------------------------------------------------------------------
// Fused weight conversion: all four [K][N]-layout weights in one launch.
// ---------------------------------------------------------------------------
#define WP_N1 (2*ND*NFF/4)      // 294912 float4 per big weight
#define WP_N4 (2*NINNER*ND/4)   // 98304
__global__ __launch_bounds__(256) void wprep_kernel(
    const float* __restrict__ wqkv, const float* __restrict__ ffw1,
    const float* __restrict__ ffw2, const float* __restrict__ wout,
    __half* __restrict__ o1, __half* __restrict__ o2,
    __half* __restrict__ o3, __half* __restrict__ o4)
{
    int i = blockIdx.x * 256 + threadIdx.x;
    const float* src; __half* dst; int j;
    if (i < WP_N1)          { src = wqkv; dst = o1; j = i; }
    else if (i < 2 * WP_N1) { src = ffw1; dst = o2; j = i - WP_N1; }
    else if (i < 3 * WP_N1) { src = ffw2; dst = o3; j = i - 2 * WP_N1; }
    else if (i < 3 * WP_N1 + WP_N4) { src = wout; dst = o4; j = i - 3 * WP_N1; }
    else return;
    st4h(dst + (size_t)j * 4, ((const float4*)src)[j]);
}

__global__ __launch_bounds__(256) void htranspose_kernel(const float* __restrict__ src,
                                                         __half* __restrict__ dst,
                                                         int R, int Cc)
{
    __shared__ float t[32][33];
    int c = blockIdx.x * 32 + threadIdx.x;
    int r = blockIdx.y * 32 + threadIdx.y;
#pragma unroll
    for (int i = 0; i < 32; i += 8)
        t[threadIdx.y + i][threadIdx.x] = src[(size_t)(r + i) * Cc + c];
    __syncthreads();
    int co = blockIdx.y * 32 + threadIdx.x;
    int ro = blockIdx.x * 32 + threadIdx.y;
#pragma unroll
    for (int i = 0; i < 32; i += 8)
        dst[(size_t)(ro + i) * R + co] = __float2half(t[threadIdx.x][threadIdx.y + i]);
}

// conv weight: lw[dout,din,k] -> wt[(k*384+din)][dout]
__global__ __launch_bounds__(256) void hwtrans_kernel(const float* __restrict__ lw,
                                                      __half* __restrict__ wt)
{
    int idx = blockIdx.x * 256 + threadIdx.x;
    if (idx >= 3 * ND * ND) return;
    int krow = idx / ND;
    int dout = idx - krow * ND;
    int k = krow / ND, din = krow - k * ND;
    wt[idx] = __float2half(lw[(dout * ND + din) * 3 + k]);
}

// ---------------------------------------------------------------------------
// Pool: x[B,C,L] -> xpT[(b*256+n), c] (half), mean over windows of 16
// ---------------------------------------------------------------------------
__global__ __launch_bounds__(256) void pool_kernel(const float* __restrict__ x,
                                                   __half* __restrict__ xpT)
{
    int bc = blockIdx.x;
    int b = bc >> 9, c = bc & 511;
    const float4* src = (const float4*)(x + (size_t)bc * NL) + threadIdx.x * 4;
    float s = 0.f;
#pragma unroll
    for (int j = 0; j < 4; j++) {
        float4 v = src[j];
        s += v.x + v.y + v.z + v.w;
    }
    xpT[((size_t)(b * NTOK + threadIdx.x)) * NC + c] = __float2half(s * (1.f / 16.f));
}

// ---------------------------------------------------------------------------
// LayerNorm over last dim (384). Warp per row. OUTH: half output.
// ---------------------------------------------------------------------------
template<int OUTH>
__global__ __launch_bounds__(256) void ln_kernel(const float* __restrict__ in,
                                                 const float* __restrict__ g,
                                                 const float* __restrict__ b,
                                                 void* __restrict__ outv)
{
    const int wid = threadIdx.x >> 5, lane = threadIdx.x & 31;
    const int row = blockIdx.x * 8 + wid;
    const float* xr = in + (size_t)row * ND;
    float4 v0 = *(const float4*)(xr + lane * 4);
    float4 v1 = *(const float4*)(xr + 128 + lane * 4);
    float4 v2 = *(const float4*)(xr + 256 + lane * 4);
    float s = v0.x + v0.y + v0.z + v0.w + v1.x + v1.y + v1.z + v1.w
            + v2.x + v2.y + v2.z + v2.w;
    float q = v0.x*v0.x + v0.y*v0.y + v0.z*v0.z + v0.w*v0.w
            + v1.x*v1.x + v1.y*v1.y + v1.z*v1.z + v1.w*v1.w
            + v2.x*v2.x + v2.y*v2.y + v2.z*v2.z + v2.w*v2.w;
#pragma unroll
    for (int o = 16; o; o >>= 1) {
        s += __shfl_xor_sync(0xFFFFFFFFu, s, o);
        q += __shfl_xor_sync(0xFFFFFFFFu, q, o);
    }
    const float mean = s * (1.f / ND);
    const float var  = q * (1.f / ND) - mean * mean;
    const float inv  = rsqrtf(var + 1e-5f);
#pragma unroll
    for (int j = 0; j < 3; j++) {
        int col = j * 128 + lane * 4;
        float4 v = (j == 0) ? v0 : (j == 1) ? v1 : v2;
        float4 gg = *(const float4*)(g + col);
        float4 bb = *(const float4*)(b + col);
        float4 r;
        r.x = (v.x - mean) * inv * gg.x + bb.x;
        r.y = (v.y - mean) * inv * gg.y + bb.y;
        r.z = (v.z - mean) * inv * gg.z + bb.z;
        r.w = (v.w - mean) * inv * gg.w + bb.w;
        if (OUTH) st4h((__half*)outv + (size_t)row * ND + col, r);
        else      *(float4*)((float*)outv + (size_t)row * ND + col) = r;
    }
}

// ---------------------------------------------------------------------------
// Linear attention per (b,h); half in (qkv), half out. Internal fp32.
// ---------------------------------------------------------------------------
__device__ __forceinline__ void r1u(float (&acc)[4][4], float a0, float a1,
                                    float a2, float a3, const float4 b)
{
    acc[0][0] += a0 * b.x; acc[0][1] += a0 * b.y; acc[0][2] += a0 * b.z; acc[0][3] += a0 * b.w;
    acc[1][0] += a1 * b.x; acc[1][1] += a1 * b.y; acc[1][2] += a1 * b.z; acc[1][3] += a1 * b.w;
    acc[2][0] += a2 * b.x; acc[2][1] += a2 * b.y; acc[2][2] += a2 * b.z; acc[2][3] += a2 * b.w;
    acc[3][0] += a3 * b.x; acc[3][1] += a3 * b.y; acc[3][2] += a3 * b.z; acc[3][3] += a3 * b.w;
}

__global__ __launch_bounds__(256) void attn_kernel(const __half* __restrict__ qkv,
                                                   const float* __restrict__ rf,
                                                   __half* __restrict__ o)
{
    __shared__ float rf_s[4096];
    __shared__ float bufA[4096];
    __shared__ float bufB[4096];
    const int tid = threadIdx.x;
    const int bh = blockIdx.x;
    const int b = bh >> 3, h = bh & 7;
    const int tq = tid >> 4, tr = tid & 15;

#pragma unroll
    for (int j = 0; j < 4; j++)
        ((float4*)rf_s)[tid + j * 256] = ((const float4*)rf)[tid + j * 256];

    const __half* base = qkv + (size_t)b * NTOK * NFF + h * NDH;

    float kv[4][4];
#pragma unroll
    for (int i = 0; i < 4; i++)
#pragma unroll
        for (int j = 0; j < 4; j++) kv[i][j] = 0.f;

    for (int n0 = 0; n0 < NTOK; n0 += 64) {
        __syncthreads();
#pragma unroll
        for (int j = 0; j < 4; j++) {
            int lin = tid + j * 256;
            int rowi = lin >> 4, c4 = (lin & 15) << 2;
            const __half* rp = base + (size_t)(n0 + rowi) * NFF;
            float4 kk = ld4h(rp + NINNER + c4);
            kk.x = fmaxf(kk.x, 0.f); kk.y = fmaxf(kk.y, 0.f);
            kk.z = fmaxf(kk.z, 0.f); kk.w = fmaxf(kk.w, 0.f);
            *(float4*)&bufA[rowi * 64 + c4] = kk;
            *(float4*)&bufB[rowi * 64 + c4] = ld4h(rp + 2 * NINNER + c4);
        }
        __syncthreads();
#pragma unroll 8
        for (int nn = 0; nn < 64; nn++) {
            float4 ka = *(const float4*)&bufA[nn * 64 + tq * 4];
            float4 vb = *(const float4*)&bufB[nn * 64 + tr * 4];
            r1u(kv, ka.x, ka.y, ka.z, ka.w, vb);
        }
    }
    __syncthreads();
#pragma unroll
    for (int i = 0; i < 4; i++) {
        float4 v = make_float4(kv[i][0], kv[i][1], kv[i][2], kv[i][3]);
        *(float4*)&bufA[(tq * 4 + i) * 64 + tr * 4] = v;
    }
    __syncthreads();

    float w1[4][4];
#pragma unroll
    for (int i = 0; i < 4; i++)
#pragma unroll
        for (int j = 0; j < 4; j++) w1[i][j] = 0.f;
#pragma unroll 8
    for (int dk = 0; dk < 64; dk++) {
        float4 rm = *(const float4*)&rf_s[dk * 64 + tq * 4];
        float4 kd = *(const float4*)&bufA[dk * 64 + tr * 4];
        r1u(w1, rm.x, rm.y, rm.z, rm.w, kd);
    }
    __syncthreads();
#pragma unroll
    for (int i = 0; i < 4; i++) {
        float4 v = make_float4(w1[i][0], w1[i][1], w1[i][2], w1[i][3]);
        *(float4*)&bufB[(tq * 4 + i) * 64 + tr * 4] = v;
    }
    __syncthreads();

    float w2[4][4];
#pragma unroll
    for (int i = 0; i < 4; i++)
#pragma unroll
        for (int j = 0; j < 4; j++) w2[i][j] = 0.f;
#pragma unroll 8
    for (int m = 0; m < 64; m++) {
        float4 wd = *(const float4*)&bufB[m * 64 + tr * 4];
        float r0 = rf_s[(tq * 4 + 0) * 64 + m];
        float r1 = rf_s[(tq * 4 + 1) * 64 + m];
        float r2 = rf_s[(tq * 4 + 2) * 64 + m];
        float r3 = rf_s[(tq * 4 + 3) * 64 + m];
        r1u(w2, r0, r1, r2, r3, wd);
    }
    __syncthreads();
#pragma unroll
    for (int i = 0; i < 4; i++) {
        float4 v = make_float4(w2[i][0], w2[i][1], w2[i][2], w2[i][3]);
        *(float4*)&bufA[(tq * 4 + i) * 64 + tr * 4] = v;
    }
    __syncthreads();

    for (int n0 = 0; n0 < NTOK; n0 += 64) {
#pragma unroll
        for (int j = 0; j < 4; j++) {
            int lin = tid + j * 256;
            int rowi = lin >> 4, c4 = (lin & 15) << 2;
            const __half* rp = base + (size_t)(n0 + rowi) * NFF;
            float4 qq = ld4h(rp + c4);
            qq.x = fmaxf(qq.x, 0.f) * 0.125f; qq.y = fmaxf(qq.y, 0.f) * 0.125f;
            qq.z = fmaxf(qq.z, 0.f) * 0.125f; qq.w = fmaxf(qq.w, 0.f) * 0.125f;
            *(float4*)&bufB[rowi * 64 + c4] = qq;
        }
        __syncthreads();
        float oc[4][4];
#pragma unroll
        for (int i = 0; i < 4; i++)
#pragma unroll
            for (int j = 0; j < 4; j++) oc[i][j] = 0.f;
#pragma unroll 8
        for (int dq = 0; dq < 64; dq++) {
            float4 wd = *(const float4*)&bufA[dq * 64 + tr * 4];
            float q0 = bufB[(tq * 4 + 0) * 64 + dq];
            float q1 = bufB[(tq * 4 + 1) * 64 + dq];
            float q2 = bufB[(tq * 4 + 2) * 64 + dq];
            float q3 = bufB[(tq * 4 + 3) * 64 + dq];
            r1u(oc, q0, q1, q2, q3, wd);
        }
#pragma unroll
        for (int i = 0; i < 4; i++) {
            st4h(o + (size_t)(b * NTOK + n0 + tq * 4 + i) * NINNER + h * NDH + tr * 4,
                 make_float4(oc[i][0], oc[i][1], oc[i][2], oc[i][3]));
        }
        __syncthreads();
    }
}

// ---------------------------------------------------------------------------
// Conv gather (half out): A_ext[r] = [h[r-1] | h[r] | h[r+1]], batch-edge zeros
// ---------------------------------------------------------------------------
__global__ __launch_bounds__(256) void gather_kernel(const float* __restrict__ h,
                                                     __half* __restrict__ aext)
{
    int idx = blockIdx.x * 256 + threadIdx.x;   // 4-elem group index
    int r = idx / 288;
    int c4 = idx - r * 288;
    int seg = c4 / 96;
    int col = (c4 - seg * 96) * 4;
    int n = r & 255;
    int src = r + seg - 1;
    float4 v = make_float4(0.f, 0.f, 0.f, 0.f);
    bool ok = (seg == 1) || (seg == 0 && n > 0) || (seg == 2 && n < 255);
    if (ok) v = *(const float4*)(h + (size_t)src * ND + col);
    st4h(aext + (size_t)r * 1152 + c4 * 4, v);
}

// ---------------------------------------------------------------------------
// Final: out[b,c,l] = interp(hp)[b,c,l] + x[b,c,l]
// ---------------------------------------------------------------------------
__global__ __launch_bounds__(256) void final_kernel(const float* __restrict__ hp,
                                                    const float* __restrict__ x,
                                                    float* __restrict__ out)
{
    size_t idx = (size_t)blockIdx.x * 256 + threadIdx.x;
    int l = (int)(idx & 4095);
    int c = (int)((idx >> 12) & 511);
    int b = (int)(idx >> 21);
    float src = fmaxf((l + 0.5f) * 0.0625f - 0.5f, 0.f);
    int i0 = (int)src;
    float w = src - (float)i0;
    int i1 = min(i0 + 1, 255);
    float v0 = hp[(size_t)(b * NTOK + i0) * NC + c];
    float v1 = hp[(size_t)(b * NTOK + i1) * NC + c];
    out[idx] = v0 * (1.f - w) + v1 * w + x[idx];
}

// ---------------------------------------------------------------------------
// Host orchestration
// ---------------------------------------------------------------------------
extern "C" void kernel_launch(void* const* d_in, const int* in_sizes, int n_in,
                              void* d_out, int out_size)
{
    const float* x          = (const float*)d_in[0];
    const float* proj_in_w  = (const float*)d_in[1];
    const float* proj_in_b  = (const float*)d_in[2];
    const float* norm_in_g  = (const float*)d_in[3];
    const float* norm_in_b  = (const float*)d_in[4];
    const float* ln1_g      = (const float*)d_in[5];
    const float* ln1_b      = (const float*)d_in[6];
    const float* wqkv       = (const float*)d_in[7];
    const float* rf         = (const float*)d_in[8];
    const float* wout       = (const float*)d_in[9];
    const float* bout       = (const float*)d_in[10];
    const float* ln2_g      = (const float*)d_in[11];
    const float* ln2_b      = (const float*)d_in[12];
    const float* ffw1       = (const float*)d_in[13];
    const float* ffb1       = (const float*)d_in[14];
    const float* ffw2       = (const float*)d_in[15];
    const float* ffb2       = (const float*)d_in[16];
    const float* local_w    = (const float*)d_in[17];
    const float* local_b    = (const float*)d_in[18];
    const float* norm_out_g = (const float*)d_in[19];
    const float* norm_out_b = (const float*)d_in[20];
    const float* proj_out_w = (const float*)d_in[21];
    const float* proj_out_b = (const float*)d_in[22];
    float* out = (float*)d_out;

    float *h_, *t3_, *hp_;
    __half *xp_, *t2h_, *yh_;
    __half *wqkvH_, *ffw1H_, *ffw2H_, *woutH_, *wAH_, *wBH_, *wtH_;
    cudaGetSymbolAddress((void**)&h_,     g_h);
    cudaGetSymbolAddress((void**)&t3_,    g_t3);
    cudaGetSymbolAddress((void**)&hp_,    g_hp);
    cudaGetSymbolAddress((void**)&xp_,    g_xp);
    cudaGetSymbolAddress((void**)&t2h_,   g_t2h);
    cudaGetSymbolAddress((void**)&yh_,    g_yh);
    cudaGetSymbolAddress((void**)&wqkvH_, g_wqkvH);
    cudaGetSymbolAddress((void**)&ffw1H_, g_ffw1H);
    cudaGetSymbolAddress((void**)&ffw2H_, g_ffw2H);
    cudaGetSymbolAddress((void**)&woutH_, g_woutH);
    cudaGetSymbolAddress((void**)&wAH_,   g_wAH);
    cudaGetSymbolAddress((void**)&wBH_,   g_wBH);
    cudaGetSymbolAddress((void**)&wtH_,   g_wtH);

    // Weight prep: one fused convert + two transposes + conv reshape
    wprep_kernel<<<(3 * WP_N1 + WP_N4 + 255) / 256, 256>>>(
        wqkv, ffw1, ffw2, wout, wqkvH_, ffw1H_, ffw2H_, woutH_);
    htranspose_kernel<<<dim3(NC / 32, ND / 32), dim3(32, 8)>>>(proj_in_w, wAH_, ND, NC);
    htranspose_kernel<<<dim3(ND / 32, NC / 32), dim3(32, 8)>>>(proj_out_w, wBH_, NC, ND);
    hwtrans_kernel<<<(3 * ND * ND + 255) / 256, 256>>>(local_w, wtH_);

    // 1. pool -> xp (half)
    pool_kernel<<<NB * NC, 256>>>(x, xp_);
    // 2. h = xp @ wAH + proj_in_b   (M=4096, N=384, K=512) -> fp32
    hgemm<1, 0, false, 0><<<dim3(3, 64), 256>>>(
        xp_, wAH_, proj_in_b, nullptr, h_, NROWS, ND, NC);
    // 3. norm_in (fp32 residual)
    ln_kernel<0><<<NROWS / 8, 256>>>(h_, norm_in_g, norm_in_b, h_);

    for (int i = 0; i < 2; i++) {
        ln_kernel<1><<<NROWS / 8, 256>>>(h_, ln1_g + i * ND, ln1_b + i * ND, t2h_);
        hgemm<2, 0, false, 1><<<dim3(12, 32), 256>>>(
            t2h_, wqkvH_ + (size_t)i * ND * NFF, nullptr, nullptr, yh_, NROWS, NFF, ND);
        attn_kernel<<<NB * NHEADS, 256>>>(yh_, rf + i * NDH * NDH, xp_);
        hgemm<1, 0, true, 0><<<dim3(3, 64), 256>>>(
            xp_, woutH_ + (size_t)i * NINNER * ND, bout + i * ND, h_, h_, NROWS, ND, NINNER);
        ln_kernel<1><<<NROWS / 8, 256>>>(h_, ln2_g + i * ND, ln2_b + i * ND, t2h_);
        hgemm<2, 1, false, 1><<<dim3(12, 32), 256>>>(
            t2h_, ffw1H_ + (size_t)i * ND * NFF, ffb1 + i * NFF, nullptr, yh_, NROWS, NFF, ND);
        hgemm<1, 0, true, 0><<<dim3(3, 64), 256>>>(
            yh_, ffw2H_ + (size_t)i * NFF * ND, ffb2 + i * ND, h_, h_, NROWS, ND, NFF);
    }

    // local conv as one GEMM: t3 = h + gather(h) @ wtH + local_b
    gather_kernel<<<(NROWS * 288) / 256, 256>>>(h_, yh_);
    hgemm<1, 0, true, 0><<<dim3(3, 64), 256>>>(
        yh_, wtH_, local_b, h_, t3_, NROWS, ND, 3 * ND);
    // norm_out -> half (feeds proj_out)
    ln_kernel<1><<<NROWS / 8, 256>>>(t3_, norm_out_g, norm_out_b, t2h_);
    // hp = t2h @ wBH + proj_out_b   (M=4096, N=512, K=384) -> fp32
    hgemm<1, 0, false, 0><<<dim3(4, 64), 256>>>(
        t2h_, wBH_, proj_out_b, nullptr, hp_, NROWS, NC, ND);
    // interp + residual with x
    final_kernel<<<(NB * NC * NL) / 256, 256>>>(hp_, x, out);
}